// round 8
// baseline (speedup 1.0000x reference)
#include <cuda_runtime.h>
#include <cuda_fp16.h>
#include <cstdint>

// HistoGAN histogram loss via mma.sync f16 + ldmatrix, K-contiguous swizzled
// operands, KC=64, double-buffered stages, one sync per chunk, f32 MUFU rcp.
// Single fused kernel: per-batch last-CTA computes the Hellinger loss inline
// (no second launch). Config reverted to the proven occ=2 / PARTS=37 point
// (occ=3 forced spills and regressed).
//
// A-stack (128 rows, K=px): rows 0-63 = Iy*k01, rows 64-127 = Iy*k02
// B0 = k02 (64 cols), B1 = k12 (64 cols).
//   G_AB = Atop x B0, G_AC = Atop x B1, G_BC = Abot x B1
// hist0[u,v]=G_AB[u,v]; hist1[u,v]=G_AC[63-u,v]; hist2[u,v]=G_BC[63-u,63-v]
//
// SMEM operand layout: row-major, 64 f16 per row (=128B), 16B-block swizzle
// blk' = blk ^ (row & 7). Producer STS.128 conflict-free; consumer ldmatrix.x4.

#define EPSV  (6.4f / 255.0f)
#define NPIX  65536
#define PARTS 37
#define QSTEP 4.761904761904762f   /* 300/63 */
#define KC    64

#define A_OFF   0
#define B0_OFF  16384
#define B1_OFF  24576
#define STAGEB  32768
#define DSMEMB  (2 * STAGEB)

__device__ float g_G[8 * 3 * 4096];   // [B][3][64][64] raw
__device__ float g_sum[8];            // per-batch total mass
__device__ unsigned g_cnt[8];         // per-batch CTA completion counter
__device__ float g_acc;               // Hellinger sum accumulator
__device__ unsigned g_done;           // batch-loss completion counter

static __device__ __forceinline__ float rcpa(float x) {
    float r; asm("rcp.approx.f32 %0, %1;" : "=f"(r) : "f"(x)); return r;
}
static __device__ __forceinline__ uint32_t s2u(const void* p) {
    uint32_t a;
    asm("{ .reg .u64 t; cvta.to.shared.u64 t, %1; cvt.u32.u64 %0, t; }"
        : "=r"(a) : "l"(p));
    return a;
}
static __device__ __forceinline__ uint32_t packh2(float lo, float hi) {
    __half2 h = __floats2half2_rn(lo, hi);
    return *(uint32_t*)&h;
}
static __device__ __forceinline__ void sts128(uint32_t addr, uint32_t w0,
        uint32_t w1, uint32_t w2, uint32_t w3) {
    asm volatile("st.shared.v4.b32 [%0], {%1,%2,%3,%4};"
        :: "r"(addr), "r"(w0), "r"(w1), "r"(w2), "r"(w3));
}
static __device__ __forceinline__ void ldmx4(uint32_t& r0, uint32_t& r1,
        uint32_t& r2, uint32_t& r3, uint32_t addr) {
    asm volatile("ldmatrix.sync.aligned.m8n8.x4.shared.b16 {%0,%1,%2,%3}, [%4];"
        : "=r"(r0), "=r"(r1), "=r"(r2), "=r"(r3) : "r"(addr));
}
static __device__ __forceinline__ void mma16(float* c,
        uint32_t a0, uint32_t a1, uint32_t a2, uint32_t a3,
        uint32_t b0, uint32_t b1) {
    asm("mma.sync.aligned.m16n8k16.row.col.f32.f16.f16.f32 "
        "{%0,%1,%2,%3},{%4,%5,%6,%7},{%8,%9},{%0,%1,%2,%3};"
        : "+f"(c[0]), "+f"(c[1]), "+f"(c[2]), "+f"(c[3])
        : "r"(a0), "r"(a1), "r"(a2), "r"(a3), "r"(b0), "r"(b1));
}

static __device__ __forceinline__ float4 pix_math(float rr, float gg, float bb) {
    float r  = fminf(fmaxf(fmaf(rr, 0.5f, 0.5f), 0.f), 1.f);
    float g  = fminf(fmaxf(fmaf(gg, 0.5f, 0.5f), 0.f), 1.f);
    float bl = fminf(fmaxf(fmaf(bb, 0.5f, 0.5f), 0.f), 1.f);
    float iy = sqrtf(fmaf(r, r, fmaf(g, g, fmaf(bl, bl, EPSV))));
    float lr = __logf(r + EPSV), lg = __logf(g + EPSV), lb = __logf(bl + EPSV);
    return make_float4(lr - lg, lr - lb, lg - lb, iy);
}

__global__ void __launch_bounds__(192, 2)
hist_kernel(const float* __restrict__ rgbd, const float* __restrict__ th,
            float* __restrict__ out, int B) {
    extern __shared__ char dsm[];                 // 2 operand stages
    __shared__ float sd[2][3][64];                // d01/d02/d12 per pixel, x2
    __shared__ float siy[2][64];                  // Iy per pixel, x2
    __shared__ int   s_last;
    __shared__ float sh[6];

    const uint32_t smb = s2u(dsm);
    const int tid  = threadIdx.x;
    const int lane = tid & 31;
    const int w    = tid >> 5;
    const int b    = blockIdx.x / PARTS;
    const int part = blockIdx.x % PARTS;
    const int start = (int)((long long)part       * NPIX / PARTS);
    const int end   = (int)((long long)(part + 1) * NPIX / PARTS);
    const float* R  = rgbd + (size_t)b * 4 * NPIX;

    // ---- producer mapping: vec = tid>>6 (0:A-top, 1:B0+A-bot, 2:B1) ----
    const int   vec  = tid >> 6;
    const int   bin  = tid & 63;
    const float negd = 150.0f - (float)bin * QSTEP;
    const int   swp  = bin & 7;
    uint32_t dst1, dst2 = 0;
    if (vec == 0)      { dst1 = A_OFF  + bin * 128; }
    else if (vec == 1) { dst1 = B0_OFF + bin * 128; dst2 = A_OFF + (64 + bin) * 128; }
    else               { dst1 = B1_OFF + bin * 128; }

    // ---- consumer mapping: warp -> matrix m, row-half rh ----
    const int m  = w >> 1;                 // 0=AB, 1=AC, 2=BC
    const int rh = w & 1;
    const int Rb = ((m == 2) ? 64 : 0) + 32 * rh;
    const uint32_t Boff = (m == 0) ? B0_OFF : B1_OFF;
    const int rowA  = Rb + (lane & 7) + 8 * ((lane >> 3) & 1);
    const int swA   = rowA & 7;
    const int koffA = lane >> 4;
    const uint32_t byteA0 = (uint32_t)(A_OFF + rowA * 128);
    const uint32_t byteA1 = byteA0 + 16 * 128;
    const int colB  = (lane & 7) + ((lane >> 1) & 8);
    const int swB   = lane & 7;
    const int koffB = (lane >> 3) & 1;
    const uint32_t byteBbase = Boff + (uint32_t)colB * 128;

    float acc[2][8][4];
#pragma unroll
    for (int s = 0; s < 2; ++s)
#pragma unroll
        for (int t = 0; t < 8; ++t)
#pragma unroll
            for (int i = 0; i < 4; ++i) acc[s][t][i] = 0.f;

    const int nch = (end - start + KC - 1) / KC;

    // pixel prep for chunk 0 (warps 4,5)
    if (tid >= 128) {
        const int q = tid - 128;
        const int px = start + q;
        float4 P = make_float4(0.f, 0.f, 0.f, 0.f);
        if (px < end) P = pix_math(R[px], R[NPIX + px], R[2 * NPIX + px]);
        sd[0][0][q] = P.x; sd[0][1][q] = P.y; sd[0][2][q] = P.z; siy[0][q] = P.w;
    }
    __syncthreads();

    for (int c = 0; c < nch; ++c) {
        const int buf = c & 1;
        const uint32_t stg = smb + buf * STAGEB;

        // early LDG for next chunk's pixels
        float rr = 0.f, gg = 0.f, bb = 0.f;
        int pvalid = 0;
        if (tid >= 128 && c + 1 < nch) {
            const int px = start + (c + 1) * KC + (tid - 128);
            if (px < end) {
                pvalid = 1;
                rr = R[px]; gg = R[NPIX + px]; bb = R[2 * NPIX + px];
            }
        }

        // ---- produce: 8 blocks of 8 pixels, STS.128 each ----
#pragma unroll
        for (int j = 0; j < 8; ++j) {
            const float4 dA = *(const float4*)&sd[buf][vec][8 * j];
            const float4 dB = *(const float4*)&sd[buf][vec][8 * j + 4];
            float k0 = rcpa(fmaf(fmaf(dA.x, 50.f, negd), fmaf(dA.x, 50.f, negd), 1.f));
            float k1 = rcpa(fmaf(fmaf(dA.y, 50.f, negd), fmaf(dA.y, 50.f, negd), 1.f));
            float k2 = rcpa(fmaf(fmaf(dA.z, 50.f, negd), fmaf(dA.z, 50.f, negd), 1.f));
            float k3 = rcpa(fmaf(fmaf(dA.w, 50.f, negd), fmaf(dA.w, 50.f, negd), 1.f));
            float k4 = rcpa(fmaf(fmaf(dB.x, 50.f, negd), fmaf(dB.x, 50.f, negd), 1.f));
            float k5 = rcpa(fmaf(fmaf(dB.y, 50.f, negd), fmaf(dB.y, 50.f, negd), 1.f));
            float k6 = rcpa(fmaf(fmaf(dB.z, 50.f, negd), fmaf(dB.z, 50.f, negd), 1.f));
            float k7 = rcpa(fmaf(fmaf(dB.w, 50.f, negd), fmaf(dB.w, 50.f, negd), 1.f));
            const uint32_t off = (uint32_t)(((j ^ swp) << 4));
            if (vec == 2) {
                sts128(stg + dst1 + off,
                       packh2(k0, k1), packh2(k2, k3),
                       packh2(k4, k5), packh2(k6, k7));
            } else {
                const float4 iA = *(const float4*)&siy[buf][8 * j];
                const float4 iB = *(const float4*)&siy[buf][8 * j + 4];
                if (vec == 1)   // raw k02 -> B0
                    sts128(stg + dst1 + off,
                           packh2(k0, k1), packh2(k2, k3),
                           packh2(k4, k5), packh2(k6, k7));
                const uint32_t dA2 = (vec == 0) ? (stg + dst1 + off) : (stg + dst2 + off);
                sts128(dA2,
                       packh2(k0 * iA.x, k1 * iA.y), packh2(k2 * iA.z, k3 * iA.w),
                       packh2(k4 * iB.x, k5 * iB.y), packh2(k6 * iB.z, k7 * iB.w));
            }
        }

        // finish pixel prep for next chunk into the other buffers
        if (tid >= 128 && c + 1 < nch) {
            float4 P = make_float4(0.f, 0.f, 0.f, 0.f);
            if (pvalid) P = pix_math(rr, gg, bb);
            const int q = tid - 128;
            sd[buf ^ 1][0][q] = P.x; sd[buf ^ 1][1][q] = P.y;
            sd[buf ^ 1][2][q] = P.z; siy[buf ^ 1][q] = P.w;
        }
        __syncthreads();

        // ---- MMA: 4 k16 steps via ldmatrix.x4, loads batched up front ----
#pragma unroll
        for (int ks = 0; ks < 4; ++ks) {
            uint32_t a0[4], a1[4], bm[4][4];
            const uint32_t kxA = (uint32_t)(((2 * ks + koffA) ^ swA) << 4);
            const uint32_t kxB = (uint32_t)(((2 * ks + koffB) ^ swB) << 4);
            ldmx4(a0[0], a0[1], a0[2], a0[3], stg + byteA0 + kxA);
            ldmx4(a1[0], a1[1], a1[2], a1[3], stg + byteA1 + kxA);
#pragma unroll
            for (int j = 0; j < 4; ++j)
                ldmx4(bm[j][0], bm[j][1], bm[j][2], bm[j][3],
                      stg + byteBbase + (uint32_t)(16 * j * 128) + kxB);
#pragma unroll
            for (int j = 0; j < 4; ++j) {
                mma16(acc[0][2 * j],     a0[0], a0[1], a0[2], a0[3], bm[j][0], bm[j][1]);
                mma16(acc[0][2 * j + 1], a0[0], a0[1], a0[2], a0[3], bm[j][2], bm[j][3]);
                mma16(acc[1][2 * j],     a1[0], a1[1], a1[2], a1[3], bm[j][0], bm[j][1]);
                mma16(acc[1][2 * j + 1], a1[0], a1[1], a1[2], a1[3], bm[j][2], bm[j][3]);
            }
        }
    }

    // ---- per-batch mass for normalization ----
    float lsum = 0.f;
#pragma unroll
    for (int s = 0; s < 2; ++s)
#pragma unroll
        for (int t = 0; t < 8; ++t)
#pragma unroll
            for (int i = 0; i < 4; ++i) lsum += acc[s][t][i];
#pragma unroll
    for (int o = 16; o > 0; o >>= 1) lsum += __shfl_xor_sync(~0u, lsum, o);
    if (lane == 0) atomicAdd(&g_sum[b], lsum);

    // ---- flush partial G ----
    float* Gb = g_G + (size_t)b * 3 * 4096;
    float* Gm = Gb + m * 4096;
    const int urow = 32 * rh + (lane >> 2);
    const int col  = 2 * (lane & 3);
#pragma unroll
    for (int s = 0; s < 2; ++s) {
#pragma unroll
        for (int t = 0; t < 8; ++t) {
            float* p0 = Gm + (urow + 16 * s) * 64 + 8 * t + col;
            atomicAdd(p0,              acc[s][t][0]);
            atomicAdd(p0 + 1,          acc[s][t][1]);
            atomicAdd(p0 + 8 * 64,     acc[s][t][2]);
            atomicAdd(p0 + 8 * 64 + 1, acc[s][t][3]);
        }
    }

    // ---- per-batch last CTA computes this batch's Hellinger term ----
    if (tid == 0) {
        __threadfence();
        const unsigned rank = atomicAdd(&g_cnt[b], 1u);
        s_last = (rank == PARTS - 1);
    }
    __syncthreads();
    if (!s_last) return;
    __threadfence();   // acquire: see all batch CTAs' atomics

    const float inv = 1.0f / (g_sum[b] + EPSV);
    float a = 0.f;
    for (int i = tid; i < 3 * 4096; i += 192) {
        const int cc = i >> 12;
        const int q  = i & 4095;
        const int u  = q >> 6, v = q & 63;
        int addr;
        if (cc == 0)      addr = q;
        else if (cc == 1) addr = 4096 + ((63 - u) << 6) + v;
        else              addr = 8192 + ((63 - u) << 6) + (63 - v);
        const float h = Gb[addr] * inv;
        Gb[addr] = 0.f;                       // reset for next graph replay
        const float d = sqrtf(th[i]) - sqrtf(h);
        a = fmaf(d, d, a);
    }
    if (tid == 0) { g_sum[b] = 0.f; g_cnt[b] = 0u; }

#pragma unroll
    for (int o = 16; o > 0; o >>= 1) a += __shfl_xor_sync(~0u, a, o);
    if (lane == 0) sh[w] = a;
    __syncthreads();
    if (tid == 0) {
        float s = 0.f;
#pragma unroll
        for (int i = 0; i < 6; ++i) s += sh[i];
        atomicAdd(&g_acc, s);
        __threadfence();
        const unsigned r2 = atomicAdd(&g_done, 1u);
        if (r2 == (unsigned)(B - 1)) {        // all batches done
            __threadfence();
            out[0] = sqrtf(g_acc) * (0.70710678118654752f / (float)B);
            g_acc = 0.f;
            g_done = 0u;
        }
    }
}

extern "C" void kernel_launch(void* const* d_in, const int* in_sizes, int n_in,
                              void* d_out, int out_size) {
    const float* rgbd = (const float*)d_in[0];
    const float* th   = (const float*)d_in[1];
    float* out        = (float*)d_out;

    const int B = in_sizes[0] / (4 * NPIX);   // 8

    cudaFuncSetAttribute(hist_kernel,
                         cudaFuncAttributeMaxDynamicSharedMemorySize, DSMEMB);
    hist_kernel<<<B * PARTS, 192, DSMEMB>>>(rgbd, th, out, B);
}

// round 9
// speedup vs baseline: 1.2907x; 1.2907x over previous
#include <cuda_runtime.h>
#include <cuda_fp16.h>
#include <cstdint>

// HistoGAN histogram loss via mma.sync f16 + ldmatrix, K-contiguous swizzled
// operands, KC=64, double-buffered stages, one sync per chunk, f32 MUFU rcp.
//
// Symmetric intensity fold: w = sqrt(Iy); panels q1=w*k01, q2=w*k02, q3=w*k12.
//   G_AB = q1 x q2^T, G_AC = q1 x q3^T, G_BC = q2 x q3^T   (w^2 = Iy)
// hist0[u,v]=G_AB[u,v]; hist1[u,v]=G_AC[63-u,v]; hist2[u,v]=G_BC[63-u,63-v]
//
// SMEM: 3 panels/stage, row-major 64 f16 per row (=128B), 16B-block swizzle
// blk' = blk ^ (row & 7). Producer STS.128 conflict-free; consumer ldmatrix.x4.
// A-bot and B0 both read panel q2 (same layout, different fragment shapes).

#define EPSV  (6.4f / 255.0f)
#define NPIX  65536
#define PARTS 37
#define QSTEP 4.761904761904762f   /* 300/63 */
#define KC    64

#define P0_OFF  0
#define P1_OFF  8192
#define P2_OFF  16384
#define STAGEB  24576
#define DSMEMB  (2 * STAGEB)

__device__ float g_G[8 * 3 * 4096];   // [B][3][64][64] raw
__device__ float g_sum[8];            // per-batch total mass
__device__ float g_acc;               // Hellinger sum accumulator
__device__ unsigned g_done;           // hell CTA completion counter

static __device__ __forceinline__ float rcpa(float x) {
    float r; asm("rcp.approx.f32 %0, %1;" : "=f"(r) : "f"(x)); return r;
}
static __device__ __forceinline__ uint32_t s2u(const void* p) {
    uint32_t a;
    asm("{ .reg .u64 t; cvta.to.shared.u64 t, %1; cvt.u32.u64 %0, t; }"
        : "=r"(a) : "l"(p));
    return a;
}
static __device__ __forceinline__ uint32_t packh2(float lo, float hi) {
    __half2 h = __floats2half2_rn(lo, hi);
    return *(uint32_t*)&h;
}
static __device__ __forceinline__ void sts128(uint32_t addr, uint32_t w0,
        uint32_t w1, uint32_t w2, uint32_t w3) {
    asm volatile("st.shared.v4.b32 [%0], {%1,%2,%3,%4};"
        :: "r"(addr), "r"(w0), "r"(w1), "r"(w2), "r"(w3));
}
static __device__ __forceinline__ void ldmx4(uint32_t& r0, uint32_t& r1,
        uint32_t& r2, uint32_t& r3, uint32_t addr) {
    asm volatile("ldmatrix.sync.aligned.m8n8.x4.shared.b16 {%0,%1,%2,%3}, [%4];"
        : "=r"(r0), "=r"(r1), "=r"(r2), "=r"(r3) : "r"(addr));
}
static __device__ __forceinline__ void mma16(float* c,
        uint32_t a0, uint32_t a1, uint32_t a2, uint32_t a3,
        uint32_t b0, uint32_t b1) {
    asm("mma.sync.aligned.m16n8k16.row.col.f32.f16.f16.f32 "
        "{%0,%1,%2,%3},{%4,%5,%6,%7},{%8,%9},{%0,%1,%2,%3};"
        : "+f"(c[0]), "+f"(c[1]), "+f"(c[2]), "+f"(c[3])
        : "r"(a0), "r"(a1), "r"(a2), "r"(a3), "r"(b0), "r"(b1));
}

static __device__ __forceinline__ float4 pix_math(float rr, float gg, float bb) {
    float r  = fminf(fmaxf(fmaf(rr, 0.5f, 0.5f), 0.f), 1.f);
    float g  = fminf(fmaxf(fmaf(gg, 0.5f, 0.5f), 0.f), 1.f);
    float bl = fminf(fmaxf(fmaf(bb, 0.5f, 0.5f), 0.f), 1.f);
    float iy = sqrtf(fmaf(r, r, fmaf(g, g, fmaf(bl, bl, EPSV))));
    float lr = __logf(r + EPSV), lg = __logf(g + EPSV), lb = __logf(bl + EPSV);
    return make_float4(lr - lg, lr - lb, lg - lb, sqrtf(iy));   // w = sqrt(Iy)
}

__global__ void __launch_bounds__(192, 2)
hist_kernel(const float* __restrict__ rgbd) {
    extern __shared__ char dsm[];                 // 2 operand stages
    __shared__ float sd[2][3][64];                // d01/d02/d12 per pixel, x2
    __shared__ float sw[2][64];                   // w = sqrt(Iy), x2

    const uint32_t smb = s2u(dsm);
    const int tid  = threadIdx.x;
    const int lane = tid & 31;
    const int w    = tid >> 5;
    const int b    = blockIdx.x / PARTS;
    const int part = blockIdx.x % PARTS;
    const int start = (int)((long long)part       * NPIX / PARTS);
    const int end   = (int)((long long)(part + 1) * NPIX / PARTS);
    const float* R  = rgbd + (size_t)b * 4 * NPIX;

    // ---- producer mapping: vec = tid>>6 -> panel q(vec+1) ----
    const int   vec  = tid >> 6;
    const int   bin  = tid & 63;
    const float negd = 150.0f - (float)bin * QSTEP;
    const int   swp  = bin & 7;
    const uint32_t dst = (uint32_t)(vec * 8192 + bin * 128);

    // ---- consumer mapping: warp -> matrix m, row-half rh ----
    const int m  = w >> 1;                 // 0=AB(q1xq2), 1=AC(q1xq3), 2=BC(q2xq3)
    const int rh = w & 1;
    const uint32_t Apanel = (m == 2) ? P1_OFF : P0_OFF;
    const uint32_t Boff   = (m == 0) ? P1_OFF : P2_OFF;
    const int rip   = 32 * rh + (lane & 7) + 8 * ((lane >> 3) & 1);  // row in panel
    const int swA   = rip & 7;
    const int koffA = lane >> 4;
    const uint32_t byteA0 = Apanel + (uint32_t)rip * 128;
    const uint32_t byteA1 = byteA0 + 16 * 128;
    const int colB  = (lane & 7) + ((lane >> 1) & 8);
    const int swB   = lane & 7;
    const int koffB = (lane >> 3) & 1;
    const uint32_t byteBbase = Boff + (uint32_t)colB * 128;

    float acc[2][8][4];
#pragma unroll
    for (int s = 0; s < 2; ++s)
#pragma unroll
        for (int t = 0; t < 8; ++t)
#pragma unroll
            for (int i = 0; i < 4; ++i) acc[s][t][i] = 0.f;

    const int nch = (end - start + KC - 1) / KC;

    // pixel prep for chunk 0 (warps 4,5)
    if (tid >= 128) {
        const int q = tid - 128;
        const int px = start + q;
        float4 P = make_float4(0.f, 0.f, 0.f, 0.f);
        if (px < end) P = pix_math(R[px], R[NPIX + px], R[2 * NPIX + px]);
        sd[0][0][q] = P.x; sd[0][1][q] = P.y; sd[0][2][q] = P.z; sw[0][q] = P.w;
    }
    __syncthreads();

    for (int c = 0; c < nch; ++c) {
        const int buf = c & 1;
        const uint32_t stg = smb + buf * STAGEB;

        // early LDG for next chunk's pixels
        float rr = 0.f, gg = 0.f, bb = 0.f;
        int pvalid = 0;
        if (tid >= 128 && c + 1 < nch) {
            const int px = start + (c + 1) * KC + (tid - 128);
            if (px < end) {
                pvalid = 1;
                rr = R[px]; gg = R[NPIX + px]; bb = R[2 * NPIX + px];
            }
        }

        // ---- produce: 8 blocks of 8 pixels, one STS.128 each ----
#pragma unroll
        for (int j = 0; j < 8; ++j) {
            const float4 dA = *(const float4*)&sd[buf][vec][8 * j];
            const float4 dB = *(const float4*)&sd[buf][vec][8 * j + 4];
            const float4 wA = *(const float4*)&sw[buf][8 * j];
            const float4 wB = *(const float4*)&sw[buf][8 * j + 4];
            float k0 = rcpa(fmaf(fmaf(dA.x, 50.f, negd), fmaf(dA.x, 50.f, negd), 1.f));
            float k1 = rcpa(fmaf(fmaf(dA.y, 50.f, negd), fmaf(dA.y, 50.f, negd), 1.f));
            float k2 = rcpa(fmaf(fmaf(dA.z, 50.f, negd), fmaf(dA.z, 50.f, negd), 1.f));
            float k3 = rcpa(fmaf(fmaf(dA.w, 50.f, negd), fmaf(dA.w, 50.f, negd), 1.f));
            float k4 = rcpa(fmaf(fmaf(dB.x, 50.f, negd), fmaf(dB.x, 50.f, negd), 1.f));
            float k5 = rcpa(fmaf(fmaf(dB.y, 50.f, negd), fmaf(dB.y, 50.f, negd), 1.f));
            float k6 = rcpa(fmaf(fmaf(dB.z, 50.f, negd), fmaf(dB.z, 50.f, negd), 1.f));
            float k7 = rcpa(fmaf(fmaf(dB.w, 50.f, negd), fmaf(dB.w, 50.f, negd), 1.f));
            const uint32_t off = (uint32_t)(((j ^ swp) << 4));
            sts128(stg + dst + off,
                   packh2(k0 * wA.x, k1 * wA.y), packh2(k2 * wA.z, k3 * wA.w),
                   packh2(k4 * wB.x, k5 * wB.y), packh2(k6 * wB.z, k7 * wB.w));
        }

        // finish pixel prep for next chunk into the other buffers
        if (tid >= 128 && c + 1 < nch) {
            float4 P = make_float4(0.f, 0.f, 0.f, 0.f);
            if (pvalid) P = pix_math(rr, gg, bb);
            const int q = tid - 128;
            sd[buf ^ 1][0][q] = P.x; sd[buf ^ 1][1][q] = P.y;
            sd[buf ^ 1][2][q] = P.z; sw[buf ^ 1][q] = P.w;
        }
        __syncthreads();

        // ---- MMA: 4 k16 steps via ldmatrix.x4, loads batched up front ----
#pragma unroll
        for (int ks = 0; ks < 4; ++ks) {
            uint32_t a0[4], a1[4], bm[4][4];
            const uint32_t kxA = (uint32_t)(((2 * ks + koffA) ^ swA) << 4);
            const uint32_t kxB = (uint32_t)(((2 * ks + koffB) ^ swB) << 4);
            ldmx4(a0[0], a0[1], a0[2], a0[3], stg + byteA0 + kxA);
            ldmx4(a1[0], a1[1], a1[2], a1[3], stg + byteA1 + kxA);
#pragma unroll
            for (int j = 0; j < 4; ++j)
                ldmx4(bm[j][0], bm[j][1], bm[j][2], bm[j][3],
                      stg + byteBbase + (uint32_t)(16 * j * 128) + kxB);
#pragma unroll
            for (int j = 0; j < 4; ++j) {
                mma16(acc[0][2 * j],     a0[0], a0[1], a0[2], a0[3], bm[j][0], bm[j][1]);
                mma16(acc[0][2 * j + 1], a0[0], a0[1], a0[2], a0[3], bm[j][2], bm[j][3]);
                mma16(acc[1][2 * j],     a1[0], a1[1], a1[2], a1[3], bm[j][0], bm[j][1]);
                mma16(acc[1][2 * j + 1], a1[0], a1[1], a1[2], a1[3], bm[j][2], bm[j][3]);
            }
        }
    }

    // ---- per-batch mass for normalization ----
    float lsum = 0.f;
#pragma unroll
    for (int s = 0; s < 2; ++s)
#pragma unroll
        for (int t = 0; t < 8; ++t)
#pragma unroll
            for (int i = 0; i < 4; ++i) lsum += acc[s][t][i];
#pragma unroll
    for (int o = 16; o > 0; o >>= 1) lsum += __shfl_xor_sync(~0u, lsum, o);
    if (lane == 0) atomicAdd(&g_sum[b], lsum);

    // ---- flush partial G ----
    float* Gm = g_G + (size_t)b * 3 * 4096 + m * 4096;
    const int urow = 32 * rh + (lane >> 2);
    const int col  = 2 * (lane & 3);
#pragma unroll
    for (int s = 0; s < 2; ++s) {
#pragma unroll
        for (int t = 0; t < 8; ++t) {
            float* p0 = Gm + (urow + 16 * s) * 64 + 8 * t + col;
            atomicAdd(p0,              acc[s][t][0]);
            atomicAdd(p0 + 1,          acc[s][t][1]);
            atomicAdd(p0 + 8 * 64,     acc[s][t][2]);
            atomicAdd(p0 + 8 * 64 + 1, acc[s][t][3]);
        }
    }
}

// ---- Hellinger: 96 CTAs (batch x matrix x quarter); re-zeroes g_G ----
__global__ void hell_kernel(const float* __restrict__ th,
                            float* __restrict__ out, int B) {
    __shared__ float sh[8];
    const int bc  = blockIdx.x >> 2;      // batch*3 + matrix
    const int sub = blockIdx.x & 3;       // quarter
    const int b   = bc / 3, c = bc % 3;
    const float inv = 1.0f / (g_sum[b] + EPSV);
    float* Gb = g_G + (size_t)b * 3 * 4096 + c * 4096;

    float a = 0.f;
#pragma unroll
    for (int it = 0; it < 4; ++it) {
        const int i = sub * 1024 + it * 256 + threadIdx.x;
        const int u = i >> 6, v = i & 63;
        int addr;
        if (c == 0)      addr = i;
        else if (c == 1) addr = ((63 - u) << 6) + v;
        else             addr = ((63 - u) << 6) + (63 - v);
        const float h = Gb[addr] * inv;
        Gb[addr] = 0.f;                       // reset for next graph replay
        const float d = sqrtf(th[c * 4096 + i]) - sqrtf(h);
        a = fmaf(d, d, a);
    }
#pragma unroll
    for (int o = 16; o > 0; o >>= 1) a += __shfl_xor_sync(~0u, a, o);
    if ((threadIdx.x & 31) == 0) sh[threadIdx.x >> 5] = a;
    __syncthreads();
    if (threadIdx.x == 0) {
        float s = 0.f;
#pragma unroll
        for (int i = 0; i < 8; ++i) s += sh[i];
        atomicAdd(&g_acc, s);
        __threadfence();
        const unsigned rank = atomicAdd(&g_done, 1u);
        if (rank == (unsigned)(12 * B - 1)) {      // last CTA finalizes
            __threadfence();
            out[0] = sqrtf(g_acc) * (0.70710678118654752f / (float)B);
            g_acc = 0.f;
            g_done = 0u;
#pragma unroll
            for (int i = 0; i < 8; ++i) g_sum[i] = 0.f;
        }
    }
}

extern "C" void kernel_launch(void* const* d_in, const int* in_sizes, int n_in,
                              void* d_out, int out_size) {
    const float* rgbd = (const float*)d_in[0];
    const float* th   = (const float*)d_in[1];
    float* out        = (float*)d_out;

    const int B = in_sizes[0] / (4 * NPIX);   // 8

    cudaFuncSetAttribute(hist_kernel,
                         cudaFuncAttributeMaxDynamicSharedMemorySize, DSMEMB);
    hist_kernel<<<B * PARTS, 192, DSMEMB>>>(rgbd);
    hell_kernel<<<B * 12, 256>>>(th, out, B);
}

// round 10
// speedup vs baseline: 1.3985x; 1.0835x over previous
#include <cuda_runtime.h>
#include <cuda_fp16.h>
#include <cstdint>

// HistoGAN histogram loss via mma.sync f16 + ldmatrix, K-contiguous swizzled
// operands, KC=64, double-buffered stages, one sync per chunk.
// Producer uses packed fma.rn.f32x2 for q/den and f16x2 mul for the w-fold.
//
// Symmetric intensity fold: w = sqrt(Iy); panels q1=w*k01, q2=w*k02, q3=w*k12.
//   G_AB = q1 x q2^T, G_AC = q1 x q3^T, G_BC = q2 x q3^T   (w^2 = Iy)
// Flips applied AT THE EPILOGUE (pre-flipped storage):
//   hist0[u,v]=G_AB[u,v]; hist1[u,v]=G_AC[63-u,v]; hist2[u,v]=G_BC[63-u,63-v]
// so g_G holds final-orientation histograms and hell_kernel reads linearly.

#define EPSV  (6.4f / 255.0f)
#define NPIX  65536
#define PARTS 37
#define QSTEP 4.761904761904762f   /* 300/63 */
#define KC    64

#define P0_OFF  0
#define P1_OFF  8192
#define P2_OFF  16384
#define STAGEB  24576
#define DSMEMB  (2 * STAGEB)

typedef unsigned long long ull;

__device__ float g_G[8 * 3 * 4096];   // [B][3][64][64] pre-flipped hist
__device__ float g_sum[8];            // per-batch total mass
__device__ float g_acc;               // Hellinger sum accumulator
__device__ unsigned g_done;           // hell CTA completion counter

static __device__ __forceinline__ float rcpa(float x) {
    float r; asm("rcp.approx.f32 %0, %1;" : "=f"(r) : "f"(x)); return r;
}
static __device__ __forceinline__ uint32_t s2u(const void* p) {
    uint32_t a;
    asm("{ .reg .u64 t; cvta.to.shared.u64 t, %1; cvt.u32.u64 %0, t; }"
        : "=r"(a) : "l"(p));
    return a;
}
static __device__ __forceinline__ uint32_t packh2(float lo, float hi) {
    __half2 h = __floats2half2_rn(lo, hi);
    return *(uint32_t*)&h;
}
static __device__ __forceinline__ ull pk2(float v) {
    ull r; asm("mov.b64 %0, {%1, %1};" : "=l"(r) : "f"(v)); return r;
}
static __device__ __forceinline__ ull fma2(ull a, ull b, ull c) {
    ull d; asm("fma.rn.f32x2 %0, %1, %2, %3;" : "=l"(d)
               : "l"(a), "l"(b), "l"(c));
    return d;
}
static __device__ __forceinline__ float lo32(ull a) {
    return __uint_as_float((uint32_t)a);
}
static __device__ __forceinline__ float hi32(ull a) {
    return __uint_as_float((uint32_t)(a >> 32));
}
static __device__ __forceinline__ uint32_t hmul2(uint32_t a, uint32_t b) {
    uint32_t d; asm("mul.rn.f16x2 %0, %1, %2;" : "=r"(d) : "r"(a), "r"(b));
    return d;
}
static __device__ __forceinline__ void sts128(uint32_t addr, uint32_t w0,
        uint32_t w1, uint32_t w2, uint32_t w3) {
    asm volatile("st.shared.v4.b32 [%0], {%1,%2,%3,%4};"
        :: "r"(addr), "r"(w0), "r"(w1), "r"(w2), "r"(w3));
}
static __device__ __forceinline__ void ldmx4(uint32_t& r0, uint32_t& r1,
        uint32_t& r2, uint32_t& r3, uint32_t addr) {
    asm volatile("ldmatrix.sync.aligned.m8n8.x4.shared.b16 {%0,%1,%2,%3}, [%4];"
        : "=r"(r0), "=r"(r1), "=r"(r2), "=r"(r3) : "r"(addr));
}
static __device__ __forceinline__ void mma16(float* c,
        uint32_t a0, uint32_t a1, uint32_t a2, uint32_t a3,
        uint32_t b0, uint32_t b1) {
    asm("mma.sync.aligned.m16n8k16.row.col.f32.f16.f16.f32 "
        "{%0,%1,%2,%3},{%4,%5,%6,%7},{%8,%9},{%0,%1,%2,%3};"
        : "+f"(c[0]), "+f"(c[1]), "+f"(c[2]), "+f"(c[3])
        : "r"(a0), "r"(a1), "r"(a2), "r"(a3), "r"(b0), "r"(b1));
}

static __device__ __forceinline__ float4 pix_math(float rr, float gg, float bb) {
    float r  = fminf(fmaxf(fmaf(rr, 0.5f, 0.5f), 0.f), 1.f);
    float g  = fminf(fmaxf(fmaf(gg, 0.5f, 0.5f), 0.f), 1.f);
    float bl = fminf(fmaxf(fmaf(bb, 0.5f, 0.5f), 0.f), 1.f);
    float iy = sqrtf(fmaf(r, r, fmaf(g, g, fmaf(bl, bl, EPSV))));
    float lr = __logf(r + EPSV), lg = __logf(g + EPSV), lb = __logf(bl + EPSV);
    return make_float4(lr - lg, lr - lb, lg - lb, sqrtf(iy));   // w = sqrt(Iy)
}

__global__ void __launch_bounds__(192, 2)
hist_kernel(const float* __restrict__ rgbd) {
    extern __shared__ char dsm[];                     // 2 operand stages
    __shared__ __align__(16) float    sd[2][3][64];   // d01/d02/d12, x2 buf
    __shared__ __align__(16) uint32_t sw2[2][32];     // half2-packed w pairs

    const uint32_t smb = s2u(dsm);
    const int tid  = threadIdx.x;
    const int lane = tid & 31;
    const int w    = tid >> 5;
    const int b    = blockIdx.x / PARTS;
    const int part = blockIdx.x % PARTS;
    const int start = (int)((long long)part       * NPIX / PARTS);
    const int end   = (int)((long long)(part + 1) * NPIX / PARTS);
    const float* R  = rgbd + (size_t)b * 4 * NPIX;

    // ---- producer mapping: vec = tid>>6 -> panel q(vec+1) ----
    const int   vec  = tid >> 6;
    const int   bin  = tid & 63;
    const float negd = 150.0f - (float)bin * QSTEP;
    const ull NEGD2 = pk2(negd);
    const ull C50   = pk2(50.0f);
    const ull ONE2  = pk2(1.0f);
    const int swp   = bin & 7;
    const uint32_t dst = (uint32_t)(vec * 8192 + bin * 128);

    // ---- consumer mapping: warp -> matrix m, row-half rh ----
    const int m  = w >> 1;                 // 0=AB(q1xq2), 1=AC(q1xq3), 2=BC(q2xq3)
    const int rh = w & 1;
    const uint32_t Apanel = (m == 2) ? P1_OFF : P0_OFF;
    const uint32_t Boff   = (m == 0) ? P1_OFF : P2_OFF;
    const int rip   = 32 * rh + (lane & 7) + 8 * ((lane >> 3) & 1);
    const int swA   = rip & 7;
    const int koffA = lane >> 4;
    const uint32_t byteA0 = Apanel + (uint32_t)rip * 128;
    const uint32_t byteA1 = byteA0 + 16 * 128;
    const int colB  = (lane & 7) + ((lane >> 1) & 8);
    const int swB   = lane & 7;
    const int koffB = (lane >> 3) & 1;
    const uint32_t byteBbase = Boff + (uint32_t)colB * 128;

    float acc[2][8][4];
#pragma unroll
    for (int s = 0; s < 2; ++s)
#pragma unroll
        for (int t = 0; t < 8; ++t)
#pragma unroll
            for (int i = 0; i < 4; ++i) acc[s][t][i] = 0.f;

    const int nch = (end - start + KC - 1) / KC;

    // pixel prep for chunk 0 (warps 4,5)
    if (tid >= 128) {
        const int q = tid - 128;
        const int px = start + q;
        float4 P = make_float4(0.f, 0.f, 0.f, 0.f);
        if (px < end) P = pix_math(R[px], R[NPIX + px], R[2 * NPIX + px]);
        sd[0][0][q] = P.x; sd[0][1][q] = P.y; sd[0][2][q] = P.z;
        const float wo = __shfl_xor_sync(0xffffffffu, P.w, 1);
        if (!(q & 1)) sw2[0][q >> 1] = packh2(P.w, wo);
    }
    __syncthreads();

    for (int c = 0; c < nch; ++c) {
        const int buf = c & 1;
        const uint32_t stg = smb + buf * STAGEB;

        // early LDG for next chunk's pixels
        float rr = 0.f, gg = 0.f, bb = 0.f;
        int pvalid = 0;
        if (tid >= 128 && c + 1 < nch) {
            const int px = start + (c + 1) * KC + (tid - 128);
            if (px < end) {
                pvalid = 1;
                rr = R[px]; gg = R[NPIX + px]; bb = R[2 * NPIX + px];
            }
        }

        // ---- produce: 8 blocks of 8 pixels (4 pairs), one STS.128 each ----
#pragma unroll
        for (int j = 0; j < 8; ++j) {
            const ulonglong2 dP01 = *(const ulonglong2*)&sd[buf][vec][8 * j];
            const ulonglong2 dP23 = *(const ulonglong2*)&sd[buf][vec][8 * j + 4];
            const uint4 wq = *(const uint4*)&sw2[buf][4 * j];

            ull q2, e2;
            uint32_t o0, o1, o2, o3;
            q2 = fma2(dP01.x, C50, NEGD2); e2 = fma2(q2, q2, ONE2);
            o0 = hmul2(packh2(rcpa(lo32(e2)), rcpa(hi32(e2))), wq.x);
            q2 = fma2(dP01.y, C50, NEGD2); e2 = fma2(q2, q2, ONE2);
            o1 = hmul2(packh2(rcpa(lo32(e2)), rcpa(hi32(e2))), wq.y);
            q2 = fma2(dP23.x, C50, NEGD2); e2 = fma2(q2, q2, ONE2);
            o2 = hmul2(packh2(rcpa(lo32(e2)), rcpa(hi32(e2))), wq.z);
            q2 = fma2(dP23.y, C50, NEGD2); e2 = fma2(q2, q2, ONE2);
            o3 = hmul2(packh2(rcpa(lo32(e2)), rcpa(hi32(e2))), wq.w);

            const uint32_t off = (uint32_t)(((j ^ swp) << 4));
            sts128(stg + dst + off, o0, o1, o2, o3);
        }

        // finish pixel prep for next chunk into the other buffers
        if (tid >= 128 && c + 1 < nch) {
            float4 P = make_float4(0.f, 0.f, 0.f, 0.f);
            if (pvalid) P = pix_math(rr, gg, bb);
            const int q = tid - 128;
            sd[buf ^ 1][0][q] = P.x; sd[buf ^ 1][1][q] = P.y;
            sd[buf ^ 1][2][q] = P.z;
            const float wo = __shfl_xor_sync(0xffffffffu, P.w, 1);
            if (!(q & 1)) sw2[buf ^ 1][q >> 1] = packh2(P.w, wo);
        }
        __syncthreads();

        // ---- MMA: 4 k16 steps via ldmatrix.x4, loads batched up front ----
#pragma unroll
        for (int ks = 0; ks < 4; ++ks) {
            uint32_t a0[4], a1[4], bm[4][4];
            const uint32_t kxA = (uint32_t)(((2 * ks + koffA) ^ swA) << 4);
            const uint32_t kxB = (uint32_t)(((2 * ks + koffB) ^ swB) << 4);
            ldmx4(a0[0], a0[1], a0[2], a0[3], stg + byteA0 + kxA);
            ldmx4(a1[0], a1[1], a1[2], a1[3], stg + byteA1 + kxA);
#pragma unroll
            for (int j = 0; j < 4; ++j)
                ldmx4(bm[j][0], bm[j][1], bm[j][2], bm[j][3],
                      stg + byteBbase + (uint32_t)(16 * j * 128) + kxB);
#pragma unroll
            for (int j = 0; j < 4; ++j) {
                mma16(acc[0][2 * j],     a0[0], a0[1], a0[2], a0[3], bm[j][0], bm[j][1]);
                mma16(acc[0][2 * j + 1], a0[0], a0[1], a0[2], a0[3], bm[j][2], bm[j][3]);
                mma16(acc[1][2 * j],     a1[0], a1[1], a1[2], a1[3], bm[j][0], bm[j][1]);
                mma16(acc[1][2 * j + 1], a1[0], a1[1], a1[2], a1[3], bm[j][2], bm[j][3]);
            }
        }
    }

    // ---- per-batch mass for normalization ----
    float lsum = 0.f;
#pragma unroll
    for (int s = 0; s < 2; ++s)
#pragma unroll
        for (int t = 0; t < 8; ++t)
#pragma unroll
            for (int i = 0; i < 4; ++i) lsum += acc[s][t][i];
#pragma unroll
    for (int o = 16; o > 0; o >>= 1) lsum += __shfl_xor_sync(~0u, lsum, o);
    if (lane == 0) atomicAdd(&g_sum[b], lsum);

    // ---- flush partial G with flips applied (pre-flipped storage) ----
    float* Gm = g_G + (size_t)b * 3 * 4096 + m * 4096;
    const int urow = 32 * rh + (lane >> 2);
    const int col  = 2 * (lane & 3);
#pragma unroll
    for (int s = 0; s < 2; ++s) {
#pragma unroll
        for (int t = 0; t < 8; ++t) {
            const int r0 = urow + 16 * s;
            const int c0 = 8 * t + col;
            if (m == 0) {
                float* p0 = Gm + r0 * 64 + c0;
                atomicAdd(p0,           acc[s][t][0]);
                atomicAdd(p0 + 1,       acc[s][t][1]);
                atomicAdd(p0 + 512,     acc[s][t][2]);
                atomicAdd(p0 + 513,     acc[s][t][3]);
            } else if (m == 1) {        // row flip
                float* p0 = Gm + (63 - r0) * 64 + c0;
                atomicAdd(p0,           acc[s][t][0]);
                atomicAdd(p0 + 1,       acc[s][t][1]);
                atomicAdd(p0 - 512,     acc[s][t][2]);
                atomicAdd(p0 - 511,     acc[s][t][3]);
            } else {                    // row + col flip
                float* p0 = Gm + (63 - r0) * 64 + (63 - c0);
                atomicAdd(p0,           acc[s][t][0]);
                atomicAdd(p0 - 1,       acc[s][t][1]);
                atomicAdd(p0 - 512,     acc[s][t][2]);
                atomicAdd(p0 - 513,     acc[s][t][3]);
            }
        }
    }
}

// ---- Hellinger: 96 CTAs, linear float4; re-zeroes g_G; last CTA finalizes ----
__global__ void hell_kernel(const float* __restrict__ th,
                            float* __restrict__ out, int B) {
    __shared__ float sh[8];
    const int bc  = blockIdx.x >> 2;      // batch*3 + matrix
    const int sub = blockIdx.x & 3;       // quarter
    const int b   = bc / 3, c = bc % 3;
    const float inv = 1.0f / (g_sum[b] + EPSV);
    const int off = c * 4096 + (sub * 256 + threadIdx.x) * 4;
    float* Gp = g_G + (size_t)b * 3 * 4096 + off;

    const float4 h4 = *(const float4*)Gp;
    const float4 t4 = *(const float4*)(th + off);
    *(float4*)Gp = make_float4(0.f, 0.f, 0.f, 0.f);   // reset for replay

    float d0 = sqrtf(t4.x) - sqrtf(h4.x * inv);
    float d1 = sqrtf(t4.y) - sqrtf(h4.y * inv);
    float d2 = sqrtf(t4.z) - sqrtf(h4.z * inv);
    float d3 = sqrtf(t4.w) - sqrtf(h4.w * inv);
    float a = fmaf(d0, d0, fmaf(d1, d1, fmaf(d2, d2, d3 * d3)));

#pragma unroll
    for (int o = 16; o > 0; o >>= 1) a += __shfl_xor_sync(~0u, a, o);
    if ((threadIdx.x & 31) == 0) sh[threadIdx.x >> 5] = a;
    __syncthreads();
    if (threadIdx.x == 0) {
        float s = 0.f;
#pragma unroll
        for (int i = 0; i < 8; ++i) s += sh[i];
        atomicAdd(&g_acc, s);
        __threadfence();
        const unsigned rank = atomicAdd(&g_done, 1u);
        if (rank == (unsigned)(12 * B - 1)) {      // last CTA finalizes
            __threadfence();
            out[0] = sqrtf(g_acc) * (0.70710678118654752f / (float)B);
            g_acc = 0.f;
            g_done = 0u;
#pragma unroll
            for (int i = 0; i < 8; ++i) g_sum[i] = 0.f;
        }
    }
}

extern "C" void kernel_launch(void* const* d_in, const int* in_sizes, int n_in,
                              void* d_out, int out_size) {
    const float* rgbd = (const float*)d_in[0];
    const float* th   = (const float*)d_in[1];
    float* out        = (float*)d_out;

    const int B = in_sizes[0] / (4 * NPIX);   // 8

    cudaFuncSetAttribute(hist_kernel,
                         cudaFuncAttributeMaxDynamicSharedMemorySize, DSMEMB);
    hist_kernel<<<B * PARTS, 192, DSMEMB>>>(rgbd);
    hell_kernel<<<B * 12, 256>>>(th, out, B);
}